// round 5
// baseline (speedup 1.0000x reference)
#include <cuda_runtime.h>
#include <cuda_bf16.h>
#include <cuda_fp16.h>

#define IMG_H 4096
#define IMG_W 4096
#define OUT_H 4097
#define OUT_W 4097
#define TILE  32
#define HIST  35   // TILE + 3
#define INW   37   // HIST + 2 (sobel halo)
#define INP   38   // padded input row stride (words)
#define OHP   36   // s_oh row stride (uint4 entries)
#define RSP   36   // s_rs row stride (uint4 entries)

// cos(pi/8), sin(pi/8)
#define CC 0.92387953251128674f
#define SS 0.38268343236508978f

__device__ __forceinline__ unsigned int h2add(unsigned int a, unsigned int b)
{
    __half2 ha = *reinterpret_cast<__half2*>(&a);
    __half2 hb = *reinterpret_cast<__half2*>(&b);
    __half2 hr = __hadd2(ha, hb);
    return *reinterpret_cast<unsigned int*>(&hr);
}
__device__ __forceinline__ unsigned int h2add4(unsigned int a, unsigned int b,
                                               unsigned int c, unsigned int d)
{
    return h2add(h2add(a, b), h2add(c, d));
}
__device__ __forceinline__ float2 h2f2(unsigned int a)
{
    __half2 h = *reinterpret_cast<__half2*>(&a);
    return __half22float2(h);
}

__global__ __launch_bounds__(256, 5)
void sift_fused_kernel(const float* __restrict__ x, float* __restrict__ out)
{
    // rs: [hist row][x] of 8xfp16 row-sums (uint4); aliased as input tile.
    __shared__ uint4 s_rs[HIST][RSP];   // 20160 B
    __shared__ uint4 s_oh[HIST][OHP];   // 20160 B  packed one-hot (8 x fp16)
    // total 40320 B -> 5 CTAs/SM

    float* s_in = (float*)s_rs;   // [INW][INP] = 5624 B, dead after stage 2

    const int X0   = blockIdx.x * TILE;
    const int Y0   = blockIdx.y * TILE;
    const int tid  = threadIdx.x;
    const int lane = tid & 31;
    const int wrow = tid >> 5;    // 0..7

    const bool interior =
        blockIdx.x >= 1 && blockIdx.x <= 126 &&
        blockIdx.y >= 1 && blockIdx.y <= 126;

    // ---- Stage 1: load input tile (origin Y0-3, X0-3) ----
    if (interior) {
        const float* src = x + (size_t)(Y0 - 3) * IMG_W + (X0 - 3);
        #pragma unroll
        for (int it = 0; it < 5; ++it) {
            int r = wrow + 8 * it;
            if (r < INW) {
                const float* row = src + (size_t)r * IMG_W;
                s_in[r * INP + lane] = row[lane];
                if (lane < INW - 32)
                    s_in[r * INP + 32 + lane] = row[32 + lane];
            }
        }
    } else {
        #pragma unroll
        for (int it = 0; it < 5; ++it) {
            int r = wrow + 8 * it;
            if (r < INW) {
                int  gy    = Y0 - 3 + r;
                bool rowok = (gy >= 0) && (gy < IMG_H);
                int  gx    = X0 - 3 + lane;
                float v = 0.0f;
                if (rowok && gx >= 0 && gx < IMG_W)
                    v = x[(size_t)gy * IMG_W + gx];
                s_in[r * INP + lane] = v;
                if (lane < INW - 32) {
                    int gx2 = gx + 32;
                    float v2 = 0.0f;
                    if (rowok && gx2 >= 0 && gx2 < IMG_W)
                        v2 = x[(size_t)gy * IMG_W + gx2];
                    s_in[r * INP + 32 + lane] = v2;
                }
            }
        }
    }
    __syncthreads();

    // ---- Stage 2: column-sliding Sobel + argmax bin + packed one-hot ----
    // 35 columns x 7 strips of 5 rows = 245 segments; rolling row stats.
    if (tid < 245) {
        int col   = tid % 35;
        int strip = tid / 35;
        int h0    = strip * 5;
        const float* base = s_in + h0 * INP + col;

        float c0 = base[0],       c1 = base[1],       c2 = base[2];
        float d0 = c2 - c0;
        float s0 = fmaf(2.0f, c1, c0) + c2;
        c0 = base[INP]; c1 = base[INP + 1]; c2 = base[INP + 2];
        float d1 = c2 - c0;
        float s1 = fmaf(2.0f, c1, c0) + c2;

        const int  gx    = X0 - 2 + col;
        const bool colok = (gx >= 0) && (gx < IMG_W);

        #pragma unroll
        for (int r = 0; r < 5; ++r) {
            const float* rb = base + (r + 2) * INP;
            c0 = rb[0]; c1 = rb[1]; c2 = rb[2];
            float d2 = c2 - c0;
            float s2 = fmaf(2.0f, c1, c0) + c2;

            float dx = fmaf(2.0f, d1, d0) + d2;
            float dy = s2 - s0;

            float cdx = CC * dx, sdx = SS * dx;
            float cdy = CC * dy, sdy = SS * dy;
            float p  = cdx + sdy;
            float q  = sdx + cdy;
            float r2 = cdy - sdx;
            float t2 = sdy - cdx;

            float bv = p; int bi = 0;
            if ( q  > bv) { bv =  q;  bi = 1; }
            if ( r2 > bv) { bv =  r2; bi = 2; }
            if ( t2 > bv) { bv =  t2; bi = 3; }
            if (-p  > bv) { bv = -p;  bi = 4; }
            if (-q  > bv) { bv = -q;  bi = 5; }
            if (-r2 > bv) { bv = -r2; bi = 6; }
            if (-t2 > bv) { bv = -t2; bi = 7; }

            float mag = sqrtf(fmaf(dx, dx, dy * dy));
            if (!interior) {
                int gy = Y0 - 2 + h0 + r;
                if (!(colok && gy >= 0 && gy < IMG_H)) mag = 0.0f;
            }

            unsigned int hm =
                (unsigned int)__half_as_ushort(__float2half_rn(mag));
            unsigned int sh = hm << ((bi & 1) << 4);
            int w = bi >> 1;
            uint4 v;
            v.x = (w == 0) ? sh : 0u;
            v.y = (w == 1) ? sh : 0u;
            v.z = (w == 2) ? sh : 0u;
            v.w = (w == 3) ? sh : 0u;
            s_oh[h0 + r][col] = v;

            d0 = d1; d1 = d2;
            s0 = s1; s1 = s2;
        }
    }
    __syncthreads();

    // ---- Stage 3: horizontal 4-tap row sums, dense half2 adds ----
    // rs[h][x] = oh[h][x] + oh[h][x+1] + oh[h][x+2] + oh[h][x+3]
    #pragma unroll
    for (int it = 0; it < 5; ++it) {
        int e = tid + 256 * it;
        if (e < HIST * TILE) {
            int h  = e >> 5;
            int ox = e & 31;
            uint4 a = s_oh[h][ox];
            uint4 b = s_oh[h][ox + 1];
            uint4 c = s_oh[h][ox + 2];
            uint4 d = s_oh[h][ox + 3];
            uint4 r;
            r.x = h2add4(a.x, b.x, c.x, d.x);
            r.y = h2add4(a.y, b.y, c.y, d.y);
            r.z = h2add4(a.z, b.z, c.z, d.z);
            r.w = h2add4(a.w, b.w, c.w, d.w);
            s_rs[h][ox] = r;
        }
    }
    __syncthreads();

    // ---- Stage 4: vertical 4-tap sliding sum (fp32) + store 8 channels ----
    const int    gx    = X0 + lane;
    const size_t plane = (size_t)OUT_H * OUT_W;
    const int    oy0   = wrow * 4;          // 4 consecutive rows per thread

    float a0 = 0.f, a1 = 0.f, a2 = 0.f, a3 = 0.f;
    float a4 = 0.f, a5 = 0.f, a6 = 0.f, a7 = 0.f;

    #define ROW_ACC(V, SGN) do {                                          \
        uint4 _v = (V);                                                   \
        float2 _f0 = h2f2(_v.x); float2 _f1 = h2f2(_v.y);                 \
        float2 _f2 = h2f2(_v.z); float2 _f3 = h2f2(_v.w);                 \
        a0 SGN _f0.x; a1 SGN _f0.y; a2 SGN _f1.x; a3 SGN _f1.y;           \
        a4 SGN _f2.x; a5 SGN _f2.y; a6 SGN _f3.x; a7 SGN _f3.y;           \
    } while (0)

    ROW_ACC(s_rs[oy0][lane], +=);
    ROW_ACC(s_rs[oy0 + 1][lane], +=);
    ROW_ACC(s_rs[oy0 + 2][lane], +=);
    ROW_ACC(s_rs[oy0 + 3][lane], +=);

    #pragma unroll
    for (int r = 0; r < 4; r++) {
        if (r > 0) {
            ROW_ACC(s_rs[oy0 + r + 3][lane], +=);
            ROW_ACC(s_rs[oy0 + r - 1][lane], -=);
        }
        int gy = Y0 + oy0 + r;
        if (gy < OUT_H && gx < OUT_W) {
            size_t base = (size_t)gy * OUT_W + gx;
            out[0 * plane + base] = a0;
            out[1 * plane + base] = a1;
            out[2 * plane + base] = a2;
            out[3 * plane + base] = a3;
            out[4 * plane + base] = a4;
            out[5 * plane + base] = a5;
            out[6 * plane + base] = a6;
            out[7 * plane + base] = a7;
        }
    }
    #undef ROW_ACC
}

extern "C" void kernel_launch(void* const* d_in, const int* in_sizes, int n_in,
                              void* d_out, int out_size)
{
    const float* x   = (const float*)d_in[0];
    float*       out = (float*)d_out;
    dim3 grid((OUT_W + TILE - 1) / TILE, (OUT_H + TILE - 1) / TILE);  // 129 x 129
    sift_fused_kernel<<<grid, 256>>>(x, out);
}

// round 6
// speedup vs baseline: 1.0907x; 1.0907x over previous
#include <cuda_runtime.h>
#include <cuda_bf16.h>

#define IMG_H 4096
#define IMG_W 4096
#define OUT_H 4097
#define OUT_W 4097
#define TILE  32
#define HIST  35   // TILE + 3
#define INW   37   // HIST + 2 (sobel halo)
#define INP   38   // padded input row stride (words)
#define HP    37   // packed (mag|idx) row stride
#define RSW   36   // s_rs row stride in floats (16B multiple)

// cos(pi/8), sin(pi/8)
#define CC 0.92387953251128674f
#define SS 0.38268343236508978f

__global__ __launch_bounds__(256, 5)
void sift_fused_kernel(const float* __restrict__ x, float* __restrict__ out)
{
    // Channel-planar row sums: s_rs[c][h][x], row stride 36 floats (16B mult).
    __shared__ float        s_rs[8][HIST][RSW];  // 40320 B (aliased as input tile)
    __shared__ unsigned int s_pk[HIST][HP];      //  5180 B packed mag|idx
    // total 45500 B -> 5 CTAs/SM

    float* s_in = (float*)s_rs;   // [INW][INP] = 5624 B, dead after stage 2

    const int X0   = blockIdx.x * TILE;
    const int Y0   = blockIdx.y * TILE;
    const int tid  = threadIdx.x;
    const int lane = tid & 31;
    const int wrow = tid >> 5;    // 0..7

    const bool interior =
        blockIdx.x >= 1 && blockIdx.x <= 126 &&
        blockIdx.y >= 1 && blockIdx.y <= 126;

    // ---- Stage 1: load input tile (origin Y0-3, X0-3) ----
    if (interior) {
        const float* src = x + (size_t)(Y0 - 3) * IMG_W + (X0 - 3);
        #pragma unroll
        for (int it = 0; it < 5; ++it) {
            int r = wrow + 8 * it;
            if (r < INW) {
                const float* row = src + (size_t)r * IMG_W;
                s_in[r * INP + lane] = row[lane];
                if (lane < INW - 32)
                    s_in[r * INP + 32 + lane] = row[32 + lane];
            }
        }
    } else {
        #pragma unroll
        for (int it = 0; it < 5; ++it) {
            int r = wrow + 8 * it;
            if (r < INW) {
                int  gy    = Y0 - 3 + r;
                bool rowok = (gy >= 0) && (gy < IMG_H);
                int  gx    = X0 - 3 + lane;
                float v = 0.0f;
                if (rowok && gx >= 0 && gx < IMG_W)
                    v = x[(size_t)gy * IMG_W + gx];
                s_in[r * INP + lane] = v;
                if (lane < INW - 32) {
                    int gx2 = gx + 32;
                    float v2 = 0.0f;
                    if (rowok && gx2 >= 0 && gx2 < IMG_W)
                        v2 = x[(size_t)gy * IMG_W + gx2];
                    s_in[r * INP + 32 + lane] = v2;
                }
            }
        }
    }
    __syncthreads();

    // ---- Stage 2: column-sliding Sobel + argmax bin + packed store ----
    // 35 columns x 7 strips of 5 rows = 245 segments; rolling row stats.
    if (tid < 245) {
        int col   = tid % 35;
        int strip = tid / 35;
        int h0    = strip * 5;
        const float* base = s_in + h0 * INP + col;

        float c0 = base[0],       c1 = base[1],       c2 = base[2];
        float d0 = c2 - c0;
        float s0 = fmaf(2.0f, c1, c0) + c2;
        c0 = base[INP]; c1 = base[INP + 1]; c2 = base[INP + 2];
        float d1 = c2 - c0;
        float s1 = fmaf(2.0f, c1, c0) + c2;

        const int  gx    = X0 - 2 + col;
        const bool colok = (gx >= 0) && (gx < IMG_W);

        #pragma unroll
        for (int r = 0; r < 5; ++r) {
            const float* rb = base + (r + 2) * INP;
            c0 = rb[0]; c1 = rb[1]; c2 = rb[2];
            float d2 = c2 - c0;
            float s2 = fmaf(2.0f, c1, c0) + c2;

            float dx = fmaf(2.0f, d1, d0) + d2;
            float dy = s2 - s0;

            float cdx = CC * dx, sdx = SS * dx;
            float cdy = CC * dy, sdy = SS * dy;
            float p  = cdx + sdy;
            float q  = sdx + cdy;
            float r2 = cdy - sdx;
            float t2 = sdy - cdx;

            float bv = p; int bi = 0;
            if ( q  > bv) { bv =  q;  bi = 1; }
            if ( r2 > bv) { bv =  r2; bi = 2; }
            if ( t2 > bv) { bv =  t2; bi = 3; }
            if (-p  > bv) { bv = -p;  bi = 4; }
            if (-q  > bv) { bv = -q;  bi = 5; }
            if (-r2 > bv) { bv = -r2; bi = 6; }
            if (-t2 > bv) { bv = -t2; bi = 7; }

            float mag = sqrtf(fmaf(dx, dx, dy * dy));
            unsigned int bits =
                (__float_as_uint(mag) & 0xFFFFFFF8u) | (unsigned int)bi;

            if (!interior) {
                int gy = Y0 - 2 + h0 + r;
                if (!(colok && gy >= 0 && gy < IMG_H)) bits = 0u;
            }
            s_pk[h0 + r][col] = bits;

            d0 = d1; d1 = d2;
            s0 = s1; s1 = s2;
        }
    }
    __syncthreads();

    // ---- Stage 3: horizontal 4-tap row sums with one-hot scatter ----
    // rs[c][h][x] = sum_{k=0..3} hist_c(h, x+k); 8 lane-contiguous scalar STS.
    #pragma unroll
    for (int it = 0; it < 5; ++it) {
        int e = tid + 256 * it;
        if (e < HIST * TILE) {
            int h  = e >> 5;
            int ox = e & 31;
            float a0 = 0.f, a1 = 0.f, a2 = 0.f, a3 = 0.f;
            float a4 = 0.f, a5 = 0.f, a6 = 0.f, a7 = 0.f;
            #pragma unroll
            for (int k = 0; k < 4; k++) {
                unsigned int u = s_pk[h][ox + k];
                unsigned int i = u & 7u;
                float m = __uint_as_float(u & 0xFFFFFFF8u);
                if (i == 0u) a0 += m;
                if (i == 1u) a1 += m;
                if (i == 2u) a2 += m;
                if (i == 3u) a3 += m;
                if (i == 4u) a4 += m;
                if (i == 5u) a5 += m;
                if (i == 6u) a6 += m;
                if (i == 7u) a7 += m;
            }
            s_rs[0][h][ox] = a0;
            s_rs[1][h][ox] = a1;
            s_rs[2][h][ox] = a2;
            s_rs[3][h][ox] = a3;
            s_rs[4][h][ox] = a4;
            s_rs[5][h][ox] = a5;
            s_rs[6][h][ox] = a6;
            s_rs[7][h][ox] = a7;
        }
    }
    __syncthreads();

    // ---- Stage 4: per-channel vertical sliding sum, register window ----
    // warp = channel; lane = g*8 + xg : rows g*8..g*8+7, x = 4*xg..4*xg+3.
    {
        const int c  = wrow;          // channel
        const int g  = lane >> 3;     // row group 0..3
        const int xg = lane & 7;      // x group 0..7
        const int h0 = g * 8;

        const float* rsb = &s_rs[c][0][4 * xg];
        float4 w0 = *(const float4*)(rsb + (h0    ) * RSW);
        float4 w1 = *(const float4*)(rsb + (h0 + 1) * RSW);
        float4 w2 = *(const float4*)(rsb + (h0 + 2) * RSW);
        float4 w3 = *(const float4*)(rsb + (h0 + 3) * RSW);

        float4 acc = make_float4(w0.x + w1.x + w2.x + w3.x,
                                 w0.y + w1.y + w2.y + w3.y,
                                 w0.z + w1.z + w2.z + w3.z,
                                 w0.w + w1.w + w2.w + w3.w);

        const size_t plane = (size_t)OUT_H * OUT_W;
        const int    gxb   = X0 + 4 * xg;
        float* op = out + (size_t)c * plane;

        const bool xfull = (gxb + 3 < OUT_W);

        #pragma unroll
        for (int r = 0; r < 8; ++r) {
            if (r > 0) {
                float4 wn = *(const float4*)(rsb + (h0 + r + 3) * RSW);
                acc.x += wn.x - w0.x;
                acc.y += wn.y - w0.y;
                acc.z += wn.z - w0.z;
                acc.w += wn.w - w0.w;
                w0 = w1; w1 = w2; w2 = w3; w3 = wn;
            }
            int gy = Y0 + h0 + r;
            if (gy < OUT_H) {
                size_t base = (size_t)gy * OUT_W + gxb;
                if (xfull) {
                    op[base    ] = acc.x;
                    op[base + 1] = acc.y;
                    op[base + 2] = acc.z;
                    op[base + 3] = acc.w;
                } else {
                    if (gxb     < OUT_W) op[base    ] = acc.x;
                    if (gxb + 1 < OUT_W) op[base + 1] = acc.y;
                    if (gxb + 2 < OUT_W) op[base + 2] = acc.z;
                    if (gxb + 3 < OUT_W) op[base + 3] = acc.w;
                }
            }
        }
    }
}

extern "C" void kernel_launch(void* const* d_in, const int* in_sizes, int n_in,
                              void* d_out, int out_size)
{
    const float* x   = (const float*)d_in[0];
    float*       out = (float*)d_out;
    dim3 grid((OUT_W + TILE - 1) / TILE, (OUT_H + TILE - 1) / TILE);  // 129 x 129
    sift_fused_kernel<<<grid, 256>>>(x, out);
}